// round 5
// baseline (speedup 1.0000x reference)
#include <cuda_runtime.h>
#include <cuda_bf16.h>

// Problem constants (fixed by the reference).
#define B_   16
#define S_   1024
#define H_   256
#define TOUT 4096          // S * D_MAX
#define NBIN 256

// Scratch (device globals: no allocation allowed).
__device__ int g_src[B_ * TOUT];   // frame -> phoneme index (valid for j < len)
__device__ int g_len[B_];          // per-batch expanded length

// ---------------------------------------------------------------------------
// Kernel 1: per-batch inclusive cumsum of rounded durations, scatter the
// frame->phoneme map (inverse of searchsorted-right), emit lengths.
// Grid: B_ blocks of S_ threads.
// ---------------------------------------------------------------------------
__global__ void scan_scatter_kernel(const float* __restrict__ dur,
                                    float* __restrict__ out,
                                    long long out_size) {
    const int b = blockIdx.x;
    const int i = threadIdx.x;

    int d = (int)rintf(dur[b * S_ + i]);
    d = max(d, 0);

    const int lane = i & 31, warp = i >> 5;
    int v = d;
#pragma unroll
    for (int o = 1; o < 32; o <<= 1) {
        int n = __shfl_up_sync(0xffffffffu, v, o);
        if (lane >= o) v += n;
    }
    __shared__ int wsum[32];
    if (lane == 31) wsum[warp] = v;
    __syncthreads();
    if (warp == 0) {
        int w = wsum[lane];
#pragma unroll
        for (int o = 1; o < 32; o <<= 1) {
            int n = __shfl_up_sync(0xffffffffu, w, o);
            if (lane >= o) w += n;
        }
        wsum[lane] = w;
    }
    __syncthreads();
    const int csum  = v + (warp > 0 ? wsum[warp - 1] : 0);  // inclusive
    const int start = csum - d;

    for (int j = start; j < csum; ++j)
        g_src[b * TOUT + j] = i;

    if (i == S_ - 1) {
        g_len[b] = csum;
        if (out_size >= (long long)B_ * TOUT * H_ + B_)
            out[out_size - B_ + b] = (float)csum;   // lengths at tuple tail
    }
}

// ---------------------------------------------------------------------------
// Quantize: jnp.searchsorted(linspace(vmin,vmax,256), clip(v), 'left'),
// clipped to [0,255]. Closed-form ceil with +-1 fixup vs exact boundaries.
// ---------------------------------------------------------------------------
__device__ __forceinline__ int qbin(float v, float vmin, float vmax,
                                    float invstep, float step) {
    v = fminf(fmaxf(v, vmin), vmax);
    int k = (int)ceilf((v - vmin) * invstep);
    k = min(max(k, 0), NBIN - 1);
    if (k > 0 && (vmin + (float)(k - 1) * step) >= v) k--;
    else if ((vmin + (float)k * step) < v) k = min(k + 1, NBIN - 1);
    return k;
}

// ---------------------------------------------------------------------------
// Kernel 2: one warp per 4 consecutive output rows (a "quad"; quads never
// straddle a batch since TOUT % 4 == 0). Vectorized uniform scalar loads,
// up to 12 independent 128-bit loads in flight per chunk, enc-row dedup
// within the quad.
// ---------------------------------------------------------------------------
__global__ void __launch_bounds__(256)
expand4_kernel(const float4* __restrict__ enc,
               const float*  __restrict__ pitch_t,
               const float*  __restrict__ energy_t,
               const float4* __restrict__ ptab,
               const float4* __restrict__ etab,
               float4*       __restrict__ out) {
    const int w    = (blockIdx.x * blockDim.x + threadIdx.x) >> 5;  // quad id
    const int lane = threadIdx.x & 31;
    const int r0   = w << 2;                  // first row of quad
    const int b    = r0 >> 12;                // / TOUT
    const int jb   = r0 & (TOUT - 1);
    const int len  = g_len[b];

    // Uniform vector loads for 4 rows' scalars.
    const int4   s4 = *(const int4*)(g_src + r0);
    const float4 p4 = __ldg((const float4*)(pitch_t + r0));
    const float4 e4 = __ldg((const float4*)(energy_t + r0));

    const int   src[4] = { s4.x, s4.y, s4.z, s4.w };
    const float pv [4] = { p4.x, p4.y, p4.z, p4.w };
    const float ev [4] = { e4.x, e4.y, e4.z, e4.w };

    bool valid[4];
    const float4* er[4];
    const float4* pr[4];
    const float4* qr[4];
#pragma unroll
    for (int r = 0; r < 4; ++r) {
        valid[r] = (jb + r) < len;
        const int s  = min(max(src[r], 0), S_ - 1);
        const int pb = qbin(pv[r], 50.0f, 400.0f, 255.0f / 350.0f, 350.0f / 255.0f);
        const int eb = qbin(ev[r],  0.0f,   1.0f, 255.0f,          1.0f / 255.0f);
        er[r] = enc  + ((size_t)(b * S_ + s)) * (H_ / 4);
        pr[r] = ptab + (size_t)pb * (H_ / 4);
        qr[r] = etab + (size_t)eb * (H_ / 4);
    }

    bool dup[4];
    dup[0] = false;
#pragma unroll
    for (int r = 1; r < 4; ++r)
        dup[r] = valid[r] && valid[r - 1] && (src[r] == src[r - 1]);

    const size_t rowo = (size_t)r0 * (H_ / 4);

#pragma unroll
    for (int k = 0; k < 2; ++k) {
        const int c = lane + 32 * k;
        float4 a[4], p[4], q[4];
#pragma unroll
        for (int r = 0; r < 4; ++r) {
            if (valid[r]) {
                if (dup[r]) a[r] = a[r - 1];
                else        a[r] = er[r][c];
                p[r] = pr[r][c];
                q[r] = qr[r][c];
            }
        }
#pragma unroll
        for (int r = 0; r < 4; ++r) {
            float4 o;
            if (valid[r])
                o = make_float4(a[r].x + p[r].x + q[r].x,
                                a[r].y + p[r].y + q[r].y,
                                a[r].z + p[r].z + q[r].z,
                                a[r].w + p[r].w + q[r].w);
            else
                o = make_float4(0.f, 0.f, 0.f, 0.f);
            out[rowo + (size_t)r * (H_ / 4) + c] = o;
        }
    }
}

extern "C" void kernel_launch(void* const* d_in, const int* in_sizes, int n_in,
                              void* d_out, int out_size) {
    const float* enc      = (const float*)d_in[0];   // [B,S,H]
    const float* pitch_t  = (const float*)d_in[1];   // [B,TOUT]
    const float* energy_t = (const float*)d_in[2];   // [B,TOUT]
    const float* dur      = (const float*)d_in[3];   // [B,S]
    const float* ptab     = (const float*)d_in[4];   // [256,H]
    const float* etab     = (const float*)d_in[5];   // [256,H]
    float* out            = (float*)d_out;

    scan_scatter_kernel<<<B_, S_>>>(dur, out, (long long)out_size);

    const int quads  = (B_ * TOUT) / 4;   // 16384 warps
    const int blocks = quads / 8;         // 8 warps per 256-thread block
    expand4_kernel<<<blocks, 256>>>((const float4*)enc, pitch_t, energy_t,
                                    (const float4*)ptab, (const float4*)etab,
                                    (float4*)out);
}

// round 8
// speedup vs baseline: 1.5183x; 1.5183x over previous
#include <cuda_runtime.h>
#include <cuda_bf16.h>

// Problem constants (fixed by the reference).
#define B_   16
#define S_   1024
#define H_   256
#define TOUT 4096          // S * D_MAX
#define NBIN 256

// Scratch (device globals: no allocation allowed).
__device__ int g_src[B_ * TOUT];   // frame -> phoneme index (valid for j < len)
__device__ int g_len[B_];          // per-batch expanded length

// ---------------------------------------------------------------------------
// Kernel 1: per-batch inclusive cumsum of rounded durations, scatter the
// frame->phoneme map (inverse of searchsorted-right), emit lengths.
// Grid: B_ blocks of S_ threads.
// ---------------------------------------------------------------------------
__global__ void scan_scatter_kernel(const float* __restrict__ dur,
                                    float* __restrict__ out,
                                    long long out_size) {
    const int b = blockIdx.x;
    const int i = threadIdx.x;

    int d = (int)rintf(dur[b * S_ + i]);
    d = max(d, 0);

    const int lane = i & 31, warp = i >> 5;
    int v = d;
#pragma unroll
    for (int o = 1; o < 32; o <<= 1) {
        int n = __shfl_up_sync(0xffffffffu, v, o);
        if (lane >= o) v += n;
    }
    __shared__ int wsum[32];
    if (lane == 31) wsum[warp] = v;
    __syncthreads();
    if (warp == 0) {
        int w = wsum[lane];
#pragma unroll
        for (int o = 1; o < 32; o <<= 1) {
            int n = __shfl_up_sync(0xffffffffu, w, o);
            if (lane >= o) w += n;
        }
        wsum[lane] = w;
    }
    __syncthreads();
    const int csum  = v + (warp > 0 ? wsum[warp - 1] : 0);  // inclusive
    const int start = csum - d;

    for (int j = start; j < csum; ++j)
        g_src[b * TOUT + j] = i;

    if (i == S_ - 1) {
        g_len[b] = csum;
        if (out_size >= (long long)B_ * TOUT * H_ + B_)
            out[out_size - B_ + b] = (float)csum;   // lengths at tuple tail
    }
}

// ---------------------------------------------------------------------------
// Quantize: jnp.searchsorted(linspace(vmin,vmax,256), clip(v), 'left'),
// clipped to [0,255]. Closed-form ceil with +-1 fixup vs exact boundaries.
// ---------------------------------------------------------------------------
__device__ __forceinline__ int qbin(float v, float vmin, float vmax,
                                    float invstep, float step) {
    v = fminf(fmaxf(v, vmin), vmax);
    int k = (int)ceilf((v - vmin) * invstep);
    k = min(max(k, 0), NBIN - 1);
    if (k > 0 && (vmin + (float)(k - 1) * step) >= v) k--;
    else if ((vmin + (float)k * step) < v) k = min(k + 1, NBIN - 1);
    return k;
}

// ---------------------------------------------------------------------------
// Kernel 2: one warp per output row (b, j). 256 floats = 2 float4/lane.
// All 6 independent 128-bit loads are issued before any arithmetic/store
// (MLP=6) while __launch_bounds__(256, 6) caps registers at 42 to keep
// occupancy ~75% (the R5 quad variant proved occupancy is the senior term).
// ---------------------------------------------------------------------------
__global__ void __launch_bounds__(256, 6)
expand_kernel(const float4* __restrict__ enc,
              const float*  __restrict__ pitch_t,
              const float*  __restrict__ energy_t,
              const float4* __restrict__ ptab,
              const float4* __restrict__ etab,
              float4*       __restrict__ out) {
    const int w    = (blockIdx.x * blockDim.x + threadIdx.x) >> 5;  // row id
    const int lane = threadIdx.x & 31;

    const int b = w >> 12;          // / TOUT
    const int j = w & (TOUT - 1);

    const size_t rowo = (size_t)w * (H_ / 4);

    if (j >= g_len[b]) {
        const float4 z = make_float4(0.f, 0.f, 0.f, 0.f);
        out[rowo + lane]      = z;
        out[rowo + lane + 32] = z;
        return;
    }

    const int src = g_src[w];
    const float pv = __ldg(pitch_t + w);
    const float ev = __ldg(energy_t + w);
    const int pb = qbin(pv, 50.0f, 400.0f, 255.0f / 350.0f, 350.0f / 255.0f);
    const int eb = qbin(ev,  0.0f,   1.0f, 255.0f,          1.0f / 255.0f);

    const float4* __restrict__ er = enc  + ((size_t)(b * S_ + src)) * (H_ / 4);
    const float4* __restrict__ pr = ptab + (size_t)pb * (H_ / 4);
    const float4* __restrict__ qr = etab + (size_t)eb * (H_ / 4);

    // Issue all six independent loads before consuming any of them.
    const float4 a0 = er[lane];
    const float4 p0 = pr[lane];
    const float4 q0 = qr[lane];
    const float4 a1 = er[lane + 32];
    const float4 p1 = pr[lane + 32];
    const float4 q1 = qr[lane + 32];

    out[rowo + lane] = make_float4(a0.x + p0.x + q0.x,
                                   a0.y + p0.y + q0.y,
                                   a0.z + p0.z + q0.z,
                                   a0.w + p0.w + q0.w);
    out[rowo + lane + 32] = make_float4(a1.x + p1.x + q1.x,
                                        a1.y + p1.y + q1.y,
                                        a1.z + p1.z + q1.z,
                                        a1.w + p1.w + q1.w);
}

extern "C" void kernel_launch(void* const* d_in, const int* in_sizes, int n_in,
                              void* d_out, int out_size) {
    const float* enc      = (const float*)d_in[0];   // [B,S,H]
    const float* pitch_t  = (const float*)d_in[1];   // [B,TOUT]
    const float* energy_t = (const float*)d_in[2];   // [B,TOUT]
    const float* dur      = (const float*)d_in[3];   // [B,S]
    const float* ptab     = (const float*)d_in[4];   // [256,H]
    const float* etab     = (const float*)d_in[5];   // [256,H]
    float* out            = (float*)d_out;

    scan_scatter_kernel<<<B_, S_>>>(dur, out, (long long)out_size);

    const int rows   = B_ * TOUT;        // 65536 warps
    const int blocks = rows / 8;         // 8 warps (rows) per 256-thread block
    expand_kernel<<<blocks, 256>>>((const float4*)enc, pitch_t, energy_t,
                                   (const float4*)ptab, (const float4*)etab,
                                   (float4*)out);
}